// round 9
// baseline (speedup 1.0000x reference)
#include <cuda_runtime.h>
#include <cuda_bf16.h>

// KL divergence between diagonal Gaussians, reduced to a single flat sum:
//   S = sum over all B*N elems of: log(s2/s1) + (s1 + (mask*(mu2-mu1))^2)/s2
//   out = 0.5 * S / B - n/2        (n = 256, B = 65536)
//
// Single kernel. Dynamic chunk-stealing (one 256-group chunk = 1 float4 per
// thread) to defeat the ~10% between-SM L2-die spread floor of static
// grid-stride. Last-block-done final reduction. 320MB read, float out.

#define TOT4    4194304u    // (65536*256)/4 float4 groups
#define NBLK    1184        // 8 * 148 SMs
#define NTHR    256
#define NCHUNK  (TOT4 / NTHR)   // 16384 chunks, 256 groups each

__device__ double       g_partials[NBLK];
__device__ unsigned int g_chunk  = 0;   // work-stealing cursor (reset by last block)
__device__ unsigned int g_ticket = 0;   // completion ticket  (reset by last block)

__global__ __launch_bounds__(NTHR)
void kld_kernel(const float4* __restrict__ mu1,
                const float4* __restrict__ mu2,
                const float4* __restrict__ s1,
                const float4* __restrict__ s2,
                const float4* __restrict__ mask,
                float* __restrict__ out)
{
    __shared__ unsigned s_next[2];
    __shared__ double   warp_sums[NTHR / 32];
    __shared__ bool     s_is_last;

    const int tid  = threadIdx.x;
    const int lane = tid & 31;
    const int wid  = tid >> 5;

    // Prime the steal pipeline.
    if (tid == 0) s_next[0] = atomicAdd(&g_chunk, 1u);
    __syncthreads();
    unsigned c   = s_next[0];
    int      buf = 1;

    double acc = 0.0;

    while (c < NCHUNK) {
        // Prefetch next chunk id; 318-cyc atomic hides under this chunk's loads.
        if (tid == 0) s_next[buf] = atomicAdd(&g_chunk, 1u);

        const unsigned i = c * NTHR + tid;

        float4 a = mu1[i];
        float4 b = mu2[i];
        float4 p = s1[i];
        float4 q = s2[i];
        float4 m = mask[i];

        // nan_to_num on mu1
        float a0 = (a.x == a.x) ? a.x : 0.0f;
        float a1 = (a.y == a.y) ? a.y : 0.0f;
        float a2 = (a.z == a.z) ? a.z : 0.0f;
        float a3 = (a.w == a.w) ? a.w : 0.0f;

        float d0 = m.x * (b.x - a0);
        float d1 = m.y * (b.y - a1);
        float d2 = m.z * (b.z - a2);
        float d3 = m.w * (b.w - a3);

        float f0 = __logf(__fdividef(q.x, p.x)) + __fdividef(p.x + d0 * d0, q.x);
        float f1 = __logf(__fdividef(q.y, p.y)) + __fdividef(p.y + d1 * d1, q.y);
        float f2 = __logf(__fdividef(q.z, p.z)) + __fdividef(p.z + d2 * d2, q.z);
        float f3 = __logf(__fdividef(q.w, p.w)) + __fdividef(p.w + d3 * d3, q.w);

        acc += (double)((f0 + f1) + (f2 + f3));

        __syncthreads();          // s_next[buf] now valid for everyone
        c   = s_next[buf];
        buf ^= 1;
    }

    // Warp reduce (double)
    #pragma unroll
    for (int off = 16; off > 0; off >>= 1)
        acc += __shfl_down_sync(0xFFFFFFFFu, acc, off);

    if (lane == 0) warp_sums[wid] = acc;
    __syncthreads();

    if (wid == 0) {
        double v = (lane < NTHR / 32) ? warp_sums[lane] : 0.0;
        #pragma unroll
        for (int off = 4; off > 0; off >>= 1)
            v += __shfl_down_sync(0xFFFFFFFFu, v, off);
        if (lane == 0) {
            g_partials[blockIdx.x] = v;
            __threadfence();
            unsigned int t = atomicAdd(&g_ticket, 1u);
            s_is_last = (t == NBLK - 1);
        }
    }
    __syncthreads();

    if (s_is_last) {
        // Last block: sum all 1184 partials (L2-hot) and write the scalar.
        double facc = 0.0;
        for (int k = tid; k < NBLK; k += NTHR)
            facc += g_partials[k];

        #pragma unroll
        for (int off = 16; off > 0; off >>= 1)
            facc += __shfl_down_sync(0xFFFFFFFFu, facc, off);

        if (lane == 0) warp_sums[wid] = facc;
        __syncthreads();

        if (wid == 0) {
            double v = (lane < NTHR / 32) ? warp_sums[lane] : 0.0;
            #pragma unroll
            for (int off = 4; off > 0; off >>= 1)
                v += __shfl_down_sync(0xFFFFFFFFu, v, off);
            if (lane == 0) {
                out[0] = (float)(0.5 * v / 65536.0 - 128.0);
                g_chunk  = 0;   // reset for next graph replay
                g_ticket = 0;
            }
        }
    }
}

extern "C" void kernel_launch(void* const* d_in, const int* in_sizes, int n_in,
                              void* d_out, int out_size)
{
    const float4* mu1  = (const float4*)d_in[0];
    const float4* mu2  = (const float4*)d_in[1];
    const float4* s1   = (const float4*)d_in[2];
    const float4* s2   = (const float4*)d_in[3];
    const float4* mask = (const float4*)d_in[4];

    kld_kernel<<<NBLK, NTHR>>>(mu1, mu2, s1, s2, mask, (float*)d_out);
}